// round 12
// baseline (speedup 1.0000x reference)
#include <cuda_runtime.h>
#include <cuda_bf16.h>
#include <cstdint>
#include <cstddef>

#define BB 64
#define TT 512
#define EE 300
#define HH 1024
#define GG 3072
#define OO 5
#define RNB 96           // gate(3) x slice(32)

// ---------------- device scratch ----------------
__device__ float g_gx[(size_t)TT * GG * BB];            // [t][g][b]
__device__ float g_WT[EE * GG];
__device__ float g_hfp[HH * BB];                        // final h [j][b]
__device__ __align__(16) char g_Wpad[(size_t)RNB * 132096];  // padded smem-ready W images
__device__ __align__(16) char g_hT[2 * 2 * 64 * 2048];  // [slot][hi/lo][b][1024 j bf16]
__device__ float g_part[RNB * 2048];                    // [blk][32 m][64 n]
__device__ unsigned g_pflag[RNB * 32];
__device__ unsigned g_hflag[32 * 32];

// ---------------- helpers ----------------
__device__ __forceinline__ void fma2(uint64_t& a, uint64_t b, uint64_t c) {
    asm("fma.rn.f32x2 %0, %1, %2, %0;" : "+l"(a) : "l"(b), "l"(c));
}
__device__ __forceinline__ uint64_t dup2(float x) {
    uint64_t r; asm("mov.b64 %0, {%1, %1};" : "=l"(r) : "f"(x)); return r;
}
__device__ __forceinline__ void unpk(uint64_t v, float& lo, float& hi) {
    asm("mov.b64 {%0, %1}, %2;" : "=f"(lo), "=f"(hi) : "l"(v));
}
__device__ __forceinline__ unsigned ldacq(const unsigned* p) {
    unsigned v;
    asm volatile("ld.global.acquire.gpu.u32 %0, [%1];" : "=r"(v) : "l"(p) : "memory");
    return v;
}
__device__ __forceinline__ void strel(unsigned* p, unsigned v) {
    asm volatile("st.global.release.gpu.u32 [%0], %1;" :: "l"(p), "r"(v) : "memory");
}
__device__ __forceinline__ uint32_t smem_u32(const void* p) {
    uint32_t a;
    asm("{ .reg .u64 t; cvta.to.shared.u64 t, %1; cvt.u32.u64 %0, t; }" : "=r"(a) : "l"(p));
    return a;
}
__device__ __forceinline__ void cpa16(uint32_t dst, const void* src) {
    asm volatile("cp.async.cg.shared.global [%0], [%1], 16;" :: "r"(dst), "l"(src));
}
#define CP_COMMIT() asm volatile("cp.async.commit_group;" ::: "memory")
template<int N> __device__ __forceinline__ void cp_wait() {
    asm volatile("cp.async.wait_group %0;" :: "n"(N) : "memory");
}
__device__ __forceinline__ float sigf(float v) { return 1.0f / (1.0f + expf(-v)); }

// mma.sync m16n8k16 row.col f32.bf16.bf16.f32 (classic HMMA; compiles for compute_103)
__device__ __forceinline__ void hmma(float& c0, float& c1, float& c2, float& c3,
                                     uint32_t a0, uint32_t a1, uint32_t a2, uint32_t a3,
                                     uint32_t b0, uint32_t b1) {
    asm volatile("mma.sync.aligned.m16n8k16.row.col.f32.bf16.bf16.f32 "
                 "{%0,%1,%2,%3},{%4,%5,%6,%7},{%8,%9},{%0,%1,%2,%3};"
                 : "+f"(c0), "+f"(c1), "+f"(c2), "+f"(c3)
                 : "r"(a0), "r"(a1), "r"(a2), "r"(a3), "r"(b0), "r"(b1));
}

// smem map (bytes) for k_rnn
#define SW_A    2064        // padded W row stride (1024 bf16 + 16B pad)
#define OFF_ALO 66048       // 32*2064
#define SB0     132096
#define SB1     166912
#define OFF_BLO 17408       // 64*272
#define XCHO    201728
#define HOWNO   210176
#define SMEM_RNN 218624

// ---------------- prep kernels ----------------
__global__ void k_reset() {
    if (threadIdx.x < RNB) g_pflag[threadIdx.x * 32] = 0u;
    if (threadIdx.x < 32)  g_hflag[threadIdx.x * 32] = 0u;
}
__global__ void k_zero() {   // zero g_hT slot 0 (262144B) + g_hfp (262144B)
    int i = blockIdx.x * blockDim.x + threadIdx.x;
    if (i < 16384) {
        ((uint4*)g_hT)[i]  = make_uint4(0, 0, 0, 0);
        ((uint4*)g_hfp)[i] = make_uint4(0, 0, 0, 0);
    }
}
__global__ void k_transpose(const float* __restrict__ Wih) {
    int i = blockIdx.x * blockDim.x + threadIdx.x;
    if (i < EE * GG) {
        int e = i / GG, g = i - e * GG;
        g_WT[i] = Wih[(size_t)g * EE + e];
    }
}
__global__ void k_packW(const float* __restrict__ Whh) {
    for (size_t idx = (size_t)blockIdx.x * blockDim.x + threadIdx.x;
         idx < (size_t)RNB * 65536; idx += (size_t)gridDim.x * blockDim.x) {
        int k    = idx & 1023;
        int m    = (idx >> 10) & 31;
        int part = (idx >> 15) & 1;
        int bid  = idx >> 16;
        int gate = bid >> 5, s = bid & 31;
        int j = s * 32 + m;
        float w = Whh[((size_t)(gate * HH + j)) * HH + k];
        __nv_bfloat16 hi = __float2bfloat16(w);
        __nv_bfloat16 v  = part ? __float2bfloat16(w - __bfloat162float(hi)) : hi;
        *(__nv_bfloat16*)(g_Wpad + (size_t)bid * 132096 + part * OFF_ALO + m * SW_A + k * 2) = v;
    }
}

// ---------------- kernel A: gx (FFMA2, unchanged) ----------------
__global__ void __launch_bounds__(256) k_gx(const int* __restrict__ x,
                                            const float* __restrict__ emb,
                                            const float* __restrict__ bih) {
    extern __shared__ float sm[];
    float* embS = sm;
    float* Wt   = sm + EE * BB;
    const int t = blockIdx.x, tid = threadIdx.x;

    for (int i = tid; i < BB * EE; i += 256) {
        int b = i / EE, e = i - b * EE;
        embS[e * BB + b] = emb[(size_t)x[b * TT + t] * EE + e];
    }
    const int bg = tid & 31, gy = tid >> 5;

    for (int gt = 0; gt < GG / 64; gt++) {
        __syncthreads();
        for (int i = tid; i < EE * 64; i += 256) {
            int e = i >> 6, g = i & 63;
            Wt[i] = g_WT[e * GG + gt * 64 + g];
        }
        __syncthreads();
        uint64_t a0[4], a1[4];
        uint64_t z0 = dup2(0.f);
#pragma unroll
        for (int p = 0; p < 4; p++) { a0[p] = z0; a1[p] = z0; }
#pragma unroll 4
        for (int e = 0; e < EE; e++) {
            float2 eb = *(float2*)&embS[e * BB + bg * 2];
            uint64_t e0 = dup2(eb.x), e1 = dup2(eb.y);
            ulonglong2 wv0 = *(const ulonglong2*)&Wt[e * 64 + gy * 8];
            ulonglong2 wv1 = *(const ulonglong2*)&Wt[e * 64 + gy * 8 + 4];
            fma2(a0[0], wv0.x, e0); fma2(a1[0], wv0.x, e1);
            fma2(a0[1], wv0.y, e0); fma2(a1[1], wv0.y, e1);
            fma2(a0[2], wv1.x, e0); fma2(a1[2], wv1.x, e1);
            fma2(a0[3], wv1.y, e0); fma2(a1[3], wv1.y, e1);
        }
#pragma unroll
        for (int p = 0; p < 4; p++) {
            int j = gt * 64 + gy * 8 + 2 * p;
            float l0, h0, l1, h1;
            unpk(a0[p], l0, h0); unpk(a1[p], l1, h1);
            float bj = bih[j], bk = bih[j + 1];
            size_t base = ((size_t)t * GG + j) * BB + bg * 2;
            g_gx[base]          = l0 + bj;
            g_gx[base + 1]      = l1 + bj;
            g_gx[base + BB]     = h0 + bk;
            g_gx[base + BB + 1] = h1 + bk;
        }
    }
}

// ---------------- kernel B: HMMA GRU recurrence ----------------
// block = gate x 32-j slice; M=32, N=64, K=1024 (full, no k-split).
// warp: (warp&1) m-half 16, (warp>>1) n-half 32. bf16 hi/lo split, 3 products.
__global__ void __launch_bounds__(128, 1) k_rnn(const float* __restrict__ bhh) {
    extern __shared__ char smem[];
    const uint32_t sbu = smem_u32(smem);
    const int tid = threadIdx.x, lane = tid & 31, warp = tid >> 5;
    const int bid = blockIdx.x, gate = bid >> 5, s = bid & 31;
    const int gid = lane >> 2, tin = lane & 3;
    const int mbase = (warp & 1) * 16, nbase = (warp >> 1) * 32;
    float* hown = (float*)(smem + HOWNO);   // [32][66] fp32, h_prev (gate blocks)
    float* xch  = (float*)(smem + XCHO);    // [32][66] fp32, transpose staging

    {   // resident padded W image (132 KB)
        const uint4* src = (const uint4*)(g_Wpad + (size_t)bid * 132096);
        uint4* dst = (uint4*)smem;
        for (int i = tid; i < 8256; i += 128) dst[i] = src[i];
    }
    if (gate == 0) for (int i = tid; i < 32 * 66; i += 128) hown[i] = 0.f;
    __syncthreads();

    float bR[2], bZ[2], bN[2];
    if (gate == 0) {
#pragma unroll
        for (int mi = 0; mi < 2; mi++) {
            int j = s * 32 + mbase + gid + mi * 8;
            bR[mi] = bhh[j]; bZ[mi] = bhh[HH + j]; bN[mi] = bhh[2 * HH + j];
        }
    }

    const char* Ahi0 = smem + (size_t)(mbase + gid) * SW_A + tin * 4;
    const char* Alo0 = Ahi0 + OFF_ALO;

    for (int t = 0; t < TT; t++) {
        if (tid < 32) { while (ldacq(&g_hflag[tid * 32]) < (unsigned)t) { } }
        __syncthreads();

        float acc[4][4];
#pragma unroll
        for (int i = 0; i < 4; i++)
            acc[i][0] = acc[i][1] = acc[i][2] = acc[i][3] = 0.f;

        const char* hsrc = (const char*)g_hT + (size_t)(t & 1) * 262144;
        // stage chunk 0 (k 0..127): 2048 x 16B -> SB0 (padded 272B rows)
#pragma unroll
        for (int q = 0; q < 16; q++) {
            int i = tid + q * 128;
            int part = i >> 10, r = i & 1023, n = r >> 4, seg = r & 15;
            cpa16(sbu + SB0 + part * OFF_BLO + n * 272 + seg * 16,
                  hsrc + part * 131072 + n * 2048 + seg * 16);
        }
        CP_COMMIT();

        for (int c = 0; c < 8; c++) {
            cp_wait<0>();
            __syncthreads();
            if (c < 7) {
                const int nbuf = (c + 1) & 1;
#pragma unroll
                for (int q = 0; q < 16; q++) {
                    int i = tid + q * 128;
                    int part = i >> 10, r = i & 1023, n = r >> 4, seg = r & 15;
                    cpa16(sbu + (nbuf ? SB1 : SB0) + part * OFF_BLO + n * 272 + seg * 16,
                          hsrc + part * 131072 + n * 2048 + (c + 1) * 256 + seg * 16);
                }
                CP_COMMIT();
            }
            const char* Ah = Ahi0 + c * 256;
            const char* Al = Alo0 + c * 256;
            const char* Bh = smem + ((c & 1) ? SB1 : SB0) + (size_t)(nbase + gid) * 272 + tin * 4;
            const char* Bl = Bh + OFF_BLO;
#pragma unroll
            for (int kt = 0; kt < 8; kt++) {
                uint32_t ah0 = *(const uint32_t*)(Ah + kt * 32);
                uint32_t ah1 = *(const uint32_t*)(Ah + kt * 32 + 8 * SW_A);
                uint32_t ah2 = *(const uint32_t*)(Ah + kt * 32 + 16);
                uint32_t ah3 = *(const uint32_t*)(Ah + kt * 32 + 8 * SW_A + 16);
                uint32_t al0 = *(const uint32_t*)(Al + kt * 32);
                uint32_t al1 = *(const uint32_t*)(Al + kt * 32 + 8 * SW_A);
                uint32_t al2 = *(const uint32_t*)(Al + kt * 32 + 16);
                uint32_t al3 = *(const uint32_t*)(Al + kt * 32 + 8 * SW_A + 16);
#pragma unroll
                for (int nt = 0; nt < 4; nt++) {
                    uint32_t bh0 = *(const uint32_t*)(Bh + kt * 32 + nt * 8 * 272);
                    uint32_t bh1 = *(const uint32_t*)(Bh + kt * 32 + nt * 8 * 272 + 16);
                    uint32_t bl0 = *(const uint32_t*)(Bl + kt * 32 + nt * 8 * 272);
                    uint32_t bl1 = *(const uint32_t*)(Bl + kt * 32 + nt * 8 * 272 + 16);
                    hmma(acc[nt][0], acc[nt][1], acc[nt][2], acc[nt][3],
                         ah0, ah1, ah2, ah3, bh0, bh1);
                    hmma(acc[nt][0], acc[nt][1], acc[nt][2], acc[nt][3],
                         ah0, ah1, ah2, ah3, bl0, bl1);
                    hmma(acc[nt][0], acc[nt][1], acc[nt][2], acc[nt][3],
                         al0, al1, al2, al3, bh0, bh1);
                }
            }
        }

        // publish gate preacts
        {
            float* dst = &g_part[bid * 2048];
#pragma unroll
            for (int nt = 0; nt < 4; nt++) {
                int n = nbase + nt * 8 + tin * 2;
                float2 v0; v0.x = acc[nt][0]; v0.y = acc[nt][1];
                float2 v1; v1.x = acc[nt][2]; v1.y = acc[nt][3];
                __stcg((float2*)&dst[(mbase + gid) * 64 + n], v0);
                __stcg((float2*)&dst[(mbase + gid + 8) * 64 + n], v1);
            }
        }
        __threadfence();
        __syncthreads();
        if (tid == 0) strel(&g_pflag[bid * 32], (unsigned)(t + 1));

        // ---- gating (gate-0 blocks): r from own acc, z/n from siblings ----
        if (gate == 0) {
            if (tid < 96) {   // siblings need t+1; all others t (WAR on h slot)
                unsigned thr = (tid == 32 + s || tid == 64 + s) ? (unsigned)(t + 1)
                                                                : (unsigned)t;
                while (ldacq(&g_pflag[tid * 32]) < thr) { }
            }
            __syncthreads();
            const float* gx = &g_gx[(size_t)t * GG * BB];
#pragma unroll
            for (int mi = 0; mi < 2; mi++) {
                int m = mbase + gid + mi * 8;
                int j = s * 32 + m;
#pragma unroll
                for (int nt = 0; nt < 4; nt++) {
                    int n = nbase + nt * 8 + tin * 2;
                    float r0 = acc[nt][mi * 2], r1 = acc[nt][mi * 2 + 1];
                    float2 zp = __ldcg((const float2*)&g_part[(32 + s) * 2048 + m * 64 + n]);
                    float2 np = __ldcg((const float2*)&g_part[(64 + s) * 2048 + m * 64 + n]);
                    float2 xr = __ldcg((const float2*)&gx[(size_t)(0 * HH + j) * BB + n]);
                    float2 xz = __ldcg((const float2*)&gx[(size_t)(1 * HH + j) * BB + n]);
                    float2 xn = __ldcg((const float2*)&gx[(size_t)(2 * HH + j) * BB + n]);
                    float2 hp = *(const float2*)&hown[m * 66 + n];
                    float r = sigf(xr.x + r0 + bR[mi]);
                    float z = sigf(xz.x + zp.x + bZ[mi]);
                    float nn = tanhf(xn.x + r * (np.x + bN[mi]));
                    float h0 = (1.f - z) * nn + z * hp.x;
                    r  = sigf(xr.y + r1 + bR[mi]);
                    z  = sigf(xz.y + zp.y + bZ[mi]);
                    nn = tanhf(xn.y + r * (np.y + bN[mi]));
                    float h1 = (1.f - z) * nn + z * hp.y;
                    float2 hv; hv.x = h0; hv.y = h1;
                    *(float2*)&hown[m * 66 + n] = hv;
                    *(float2*)&xch[m * 66 + n]  = hv;
                }
            }
            __syncthreads();
            {   // transpose + bf16 hi/lo split -> g_hT slot (t+1)&1
                int n = tid >> 1, mh = tid & 1;
                float v[16];
#pragma unroll
                for (int i = 0; i < 16; i++) v[i] = xch[(mh * 16 + i) * 66 + n];
                uint32_t hi[8], lo[8];
#pragma unroll
                for (int p = 0; p < 8; p++) {
                    __nv_bfloat16 b0 = __float2bfloat16(v[2 * p]);
                    __nv_bfloat16 b1 = __float2bfloat16(v[2 * p + 1]);
                    __nv_bfloat162 hb; hb.x = b0; hb.y = b1;
                    hi[p] = *(uint32_t*)&hb;
                    __nv_bfloat162 lb;
                    lb.x = __float2bfloat16(v[2 * p]     - __bfloat162float(b0));
                    lb.y = __float2bfloat16(v[2 * p + 1] - __bfloat162float(b1));
                    lo[p] = *(uint32_t*)&lb;
                }
                char* dhi = (char*)g_hT + (size_t)((t + 1) & 1) * 262144
                          + n * 2048 + s * 64 + mh * 32;
                char* dlo = dhi + 131072;
                __stcg((uint4*)dhi,        *(uint4*)&hi[0]);
                __stcg((uint4*)(dhi + 16), *(uint4*)&hi[4]);
                __stcg((uint4*)dlo,        *(uint4*)&lo[0]);
                __stcg((uint4*)(dlo + 16), *(uint4*)&lo[4]);
                if (t == TT - 1) {
#pragma unroll
                    for (int i = 0; i < 16; i++)
                        g_hfp[(s * 32 + mh * 16 + i) * BB + n] = v[i];
                }
            }
            __threadfence();
            __syncthreads();
            if (tid == 0) strel(&g_hflag[s * 32], (unsigned)(t + 1));
        }
    }
}

// ---------------- kernel C: FC ----------------
__global__ void k_fc(const float* __restrict__ Wfc, const float* __restrict__ bfc,
                     float* __restrict__ out) {
    int tid = threadIdx.x;
    if (tid >= BB * OO) return;
    int b = tid & 63, o = tid >> 6;
    float a0 = 0.f, a1 = 0.f, a2 = 0.f, a3 = 0.f;
    for (int j = 0; j < HH; j += 4) {
        a0 += g_hfp[(j + 0) * BB + b] * Wfc[o * HH + j + 0];
        a1 += g_hfp[(j + 1) * BB + b] * Wfc[o * HH + j + 1];
        a2 += g_hfp[(j + 2) * BB + b] * Wfc[o * HH + j + 2];
        a3 += g_hfp[(j + 3) * BB + b] * Wfc[o * HH + j + 3];
    }
    out[b * OO + o] = a0 + a1 + a2 + a3 + bfc[o];
}

// ---------------- entry ----------------
extern "C" void kernel_launch(void* const* d_in, const int* in_sizes, int n_in,
                              void* d_out, int out_size) {
    const int*   x   = (const int*)d_in[0];
    const float* emb = (const float*)d_in[1];
    const float* Wih = (const float*)d_in[2];
    const float* Whh = (const float*)d_in[3];
    const float* bih = (const float*)d_in[4];
    const float* bhh = (const float*)d_in[5];
    const float* Wfc = (const float*)d_in[6];
    const float* bfc = (const float*)d_in[7];
    float* out = (float*)d_out;

    const int smemA = 2 * EE * BB * (int)sizeof(float);
    cudaFuncSetAttribute(k_gx,  cudaFuncAttributeMaxDynamicSharedMemorySize, smemA);
    cudaFuncSetAttribute(k_rnn, cudaFuncAttributeMaxDynamicSharedMemorySize, SMEM_RNN);

    k_reset<<<1, 128>>>();
    k_zero<<<64, 256>>>();
    k_transpose<<<(EE * GG + 255) / 256, 256>>>(Wih);
    k_packW<<<512, 256>>>(Whh);
    k_gx<<<TT, 256, smemA>>>(x, emb, bih);
    k_rnn<<<RNB, 128, SMEM_RNN>>>(bhh);
    k_fc<<<1, 512>>>(Wfc, bfc, out);
}